// round 1
// baseline (speedup 1.0000x reference)
#include <cuda_runtime.h>
#include <stdint.h>

#define B       8
#define NH      778
#define VOBJ    40000
#define THREADS 256
#define HTILES  4        // ceil(778/256)
#define OSLICES 16       // 2500 obj verts per slice
#define OSLICE  (VOBJ / OSLICES)
#define TOBJ    512      // shared tile of obj verts

__constant__ int c_contact_idx[10] = {745, 317, 444, 556, 673, 95, 182, 234, 279, 320};

// scratch: per (b, hand-vertex) running min of squared distance, as uint bits
// (all values >= 0, so IEEE float order == unsigned int order)
__device__ unsigned int g_dmin[B * NH];

__global__ void init_kernel() {
    int i = blockIdx.x * blockDim.x + threadIdx.x;
    if (i < B * NH) g_dmin[i] = 0x7f800000u;  // +inf
}

__global__ __launch_bounds__(THREADS) void mindist_kernel(
    const float* __restrict__ hand, const float* __restrict__ obj)
{
    const int b     = blockIdx.z;
    const int htile = blockIdx.x;
    const int slice = blockIdx.y;
    const int h     = htile * THREADS + threadIdx.x;
    const bool active = (h < NH);

    float ax = 0.f, ay = 0.f, az = 0.f, asq = 0.f;
    if (active) {
        const float* hp = hand + ((size_t)b * NH + h) * 3;
        ax = hp[0]; ay = hp[1]; az = hp[2];
        asq = fmaf(ax, ax, fmaf(ay, ay, az * az));
    }

    __shared__ float4 sh[TOBJ];

    const int o0 = slice * OSLICE;
    const int o1 = o0 + OSLICE;

    // two accumulators to shorten the FMNMX dependency chain
    float m0 = 3.4e38f, m1 = 3.4e38f;

    for (int base = o0; base < o1; base += TOBJ) {
        const int cnt = min(TOBJ, o1 - base);
        __syncthreads();
        for (int k = threadIdx.x; k < cnt; k += THREADS) {
            const float* op = obj + ((size_t)b * VOBJ + base + k) * 3;
            float x = op[0], y = op[1], z = op[2];
            sh[k] = make_float4(x, y, z, fmaf(x, x, fmaf(y, y, z * z)));
        }
        __syncthreads();
        if (active) {
            int j = 0;
            #pragma unroll 4
            for (; j + 1 < cnt; j += 2) {
                float4 o0v = sh[j];
                float4 o1v = sh[j + 1];
                float dot0 = fmaf(ax, o0v.x, fmaf(ay, o0v.y, az * o0v.z));
                float dot1 = fmaf(ax, o1v.x, fmaf(ay, o1v.y, az * o1v.z));
                float d20 = fmaf(-2.f, dot0, asq + o0v.w);
                float d21 = fmaf(-2.f, dot1, asq + o1v.w);
                m0 = fminf(m0, d20);
                m1 = fminf(m1, d21);
            }
            if (j < cnt) {
                float4 ov = sh[j];
                float dot = fmaf(ax, ov.x, fmaf(ay, ov.y, az * ov.z));
                m0 = fminf(m0, fmaf(-2.f, dot, asq + ov.w));
            }
        }
    }

    if (active) {
        float m = fmaxf(fminf(m0, m1), 0.f);
        atomicMin(&g_dmin[b * NH + h], __float_as_uint(m));
    }
}

// one-block final reduction producing the 6 scalar outputs
__global__ __launch_bounds__(256) void reduce_kernel(float* __restrict__ out)
{
    const int tid = threadIdx.x;
    const int N = B * NH;

    float sum_d = 0.f;
    float pen_sum = 0.f;
    int   pen_cnt = 0;

    for (int i = tid; i < N; i += 256) {
        float d = sqrtf(__uint_as_float(g_dmin[i]));
        sum_d += d;
        if (d < 0.005f) {
            float t = 0.005f - d;
            pen_sum += t * t;
            pen_cnt++;
        }
    }

    float att_sum = 0.f;
    int   att_cnt = 0;
    for (int i = tid; i < B * 10; i += 256) {
        int bb = i / 10, jj = i % 10;
        float d = sqrtf(__uint_as_float(g_dmin[bb * NH + c_contact_idx[jj]]));
        if (d > 0.005f && d < 0.01f) {
            att_sum += d * d;
            att_cnt++;
        }
    }

    // block reduction: warp shuffles then shared
    __shared__ float s_f[3][8];
    __shared__ int   s_i[2][8];
    const unsigned FULL = 0xffffffffu;
    for (int off = 16; off > 0; off >>= 1) {
        sum_d   += __shfl_down_sync(FULL, sum_d,   off);
        pen_sum += __shfl_down_sync(FULL, pen_sum, off);
        att_sum += __shfl_down_sync(FULL, att_sum, off);
        pen_cnt += __shfl_down_sync(FULL, pen_cnt, off);
        att_cnt += __shfl_down_sync(FULL, att_cnt, off);
    }
    int wid = tid >> 5, lid = tid & 31;
    if (lid == 0) {
        s_f[0][wid] = sum_d; s_f[1][wid] = pen_sum; s_f[2][wid] = att_sum;
        s_i[0][wid] = pen_cnt; s_i[1][wid] = att_cnt;
    }
    __syncthreads();
    if (tid == 0) {
        float tsum = 0.f, tpen = 0.f, tatt = 0.f;
        int   cpen = 0, catt = 0;
        #pragma unroll
        for (int w = 0; w < 8; w++) {
            tsum += s_f[0][w]; tpen += s_f[1][w]; tatt += s_f[2][w];
            cpen += s_i[0][w]; catt += s_i[1][w];
        }
        float pen_loss = (cpen > 0) ? tpen / (float)cpen : 0.f;
        float att_loss = (catt > 0) ? tatt / (float)catt : 0.f;
        float contact_loss = 100.f * pen_loss + 10.f * att_loss;
        float dist_mean = tsum / (float)N;
        out[0] = contact_loss;
        out[1] = pen_loss;
        out[2] = att_loss;
        out[3] = dist_mean;
        out[4] = (float)catt;  // num_contacts
        out[5] = (float)cpen;  // num_penetrations
    }
}

extern "C" void kernel_launch(void* const* d_in, const int* in_sizes, int n_in,
                              void* d_out, int out_size)
{
    const float* hand = (const float*)d_in[0];  // [8, 778, 3] f32
    const float* obj  = (const float*)d_in[1];  // [8, 40000, 3] f32
    // d_in[2], d_in[3] (faces) are unused by the loss
    float* out = (float*)d_out;

    init_kernel<<<(B * NH + 255) / 256, 256>>>();
    dim3 grid(HTILES, OSLICES, B);
    mindist_kernel<<<grid, THREADS>>>(hand, obj);
    reduce_kernel<<<1, 256>>>(out);
    (void)in_sizes; (void)n_in; (void)out_size;
}

// round 2
// speedup vs baseline: 1.2214x; 1.2214x over previous
#include <cuda_runtime.h>
#include <stdint.h>

#define B       8
#define NH      778
#define VOBJ    40000
#define THREADS 256
#define HTILES  4        // ceil(778/256)
#define OSLICES 25       // 1600 obj verts per slice -> 600 heavy blocks ~ 4.05/SM
#define OSLICE  (VOBJ / OSLICES)
#define TOBJ    512      // shared tile of obj verts (256 packed pairs)
#define NPAIRS  (TOBJ / 2)

__constant__ int c_contact_idx[10] = {745, 317, 444, 556, 673, 95, 182, 234, 279, 320};

// per-slice partial d^2 min: [OSLICES][B][NH]  (written every launch -> no init needed)
__device__ float g_part[OSLICES * B * NH];
// per hand-vertex final distance (for contact-idx lookup inside reduce block)
__device__ float g_d[B * NH];

__device__ __forceinline__ unsigned long long pack2(float a, float b) {
    unsigned long long r;
    asm("mov.b64 %0, {%1, %2};" : "=l"(r) : "f"(a), "f"(b));
    return r;
}
__device__ __forceinline__ unsigned long long fma2(unsigned long long a,
                                                   unsigned long long b,
                                                   unsigned long long c) {
    unsigned long long d;
    asm("fma.rn.f32x2 %0, %1, %2, %3;" : "=l"(d) : "l"(a), "l"(b), "l"(c));
    return d;
}
__device__ __forceinline__ void unpack2(unsigned long long v, float& lo, float& hi) {
    asm("mov.b64 {%0, %1}, %2;" : "=f"(lo), "=f"(hi) : "l"(v));
}

__global__ __launch_bounds__(THREADS) void mindist_kernel(
    const float* __restrict__ hand, const float* __restrict__ obj)
{
    const int b     = blockIdx.z;
    const int htile = blockIdx.x;
    const int slice = blockIdx.y;
    const int h     = htile * THREADS + threadIdx.x;
    const bool active = (h < NH);

    float ax = 0.f, ay = 0.f, az = 0.f, asq = 0.f;
    if (active) {
        const float* hp = hand + ((size_t)b * NH + h) * 3;
        ax = hp[0]; ay = hp[1]; az = hp[2];
        asq = fmaf(ax, ax, fmaf(ay, ay, az * az));
    }
    const unsigned long long axx = pack2(ax, ax);
    const unsigned long long ayy = pack2(ay, ay);
    const unsigned long long azz = pack2(az, az);

    // packed-pair SoA: shA[p] = {(-2x0,-2x1), (-2y0,-2y1)}, shB[p] = {(-2z0,-2z1), (bsq0,bsq1)}
    __shared__ ulonglong2 shA[NPAIRS];
    __shared__ ulonglong2 shB[NPAIRS];

    const int o0 = slice * OSLICE;
    const int o1 = o0 + OSLICE;

    float m[8];
    #pragma unroll
    for (int i = 0; i < 8; i++) m[i] = 3.4e38f;

    for (int base = o0; base < o1; base += TOBJ) {
        const int cnt   = min(TOBJ, o1 - base);   // 512 or 64 -> always even
        const int npair = cnt >> 1;
        __syncthreads();
        if (threadIdx.x < npair) {
            const float* op = obj + ((size_t)b * VOBJ + base + threadIdx.x * 2) * 3;
            float2 p01 = *(const float2*)(op + 0);   // x0 y0
            float2 p23 = *(const float2*)(op + 2);   // z0 x1
            float2 p45 = *(const float2*)(op + 4);   // y1 z1
            float x0 = p01.x, y0 = p01.y, z0 = p23.x;
            float x1 = p23.y, y1 = p45.x, z1 = p45.y;
            float w0 = fmaf(x0, x0, fmaf(y0, y0, z0 * z0));
            float w1 = fmaf(x1, x1, fmaf(y1, y1, z1 * z1));
            ulonglong2 A, Bv;
            A.x  = pack2(-2.f * x0, -2.f * x1);
            A.y  = pack2(-2.f * y0, -2.f * y1);
            Bv.x = pack2(-2.f * z0, -2.f * z1);
            Bv.y = pack2(w0, w1);
            shA[threadIdx.x] = A;
            shB[threadIdx.x] = Bv;
        }
        __syncthreads();
        if (active) {
            // npair is 256 or 32 -> multiple of 4
            for (int p = 0; p < npair; p += 4) {
                #pragma unroll
                for (int q = 0; q < 4; q++) {
                    ulonglong2 A  = shA[p + q];
                    ulonglong2 Bv = shB[p + q];
                    unsigned long long e =
                        fma2(A.x, axx, fma2(A.y, ayy, fma2(Bv.x, azz, Bv.y)));
                    float e0, e1;
                    unpack2(e, e0, e1);
                    m[2 * q + 0] = fminf(m[2 * q + 0], e0);
                    m[2 * q + 1] = fminf(m[2 * q + 1], e1);
                }
            }
        }
    }

    if (active) {
        float mm = fminf(fminf(fminf(m[0], m[1]), fminf(m[2], m[3])),
                         fminf(fminf(m[4], m[5]), fminf(m[6], m[7])));
        // d^2 (possibly slightly negative from rounding; clamped in reduce)
        g_part[(slice * B + b) * NH + h] = asq + mm;
    }
}

// one-block final reduction producing the 6 scalar outputs
__global__ __launch_bounds__(1024) void reduce_kernel(float* __restrict__ out)
{
    const int tid = threadIdx.x;
    const int N = B * NH;

    float sum_d = 0.f;
    float pen_sum = 0.f;
    int   pen_cnt = 0;

    for (int i = tid; i < N; i += 1024) {
        float mn = 3.4e38f;
        #pragma unroll
        for (int s = 0; s < OSLICES; s++)
            mn = fminf(mn, g_part[s * N + i]);
        float d = sqrtf(fmaxf(mn, 0.f));
        g_d[i] = d;
        sum_d += d;
        if (d < 0.005f) {
            float t = 0.005f - d;
            pen_sum += t * t;
            pen_cnt++;
        }
    }
    __syncthreads();   // make g_d visible block-wide

    float att_sum = 0.f;
    int   att_cnt = 0;
    if (tid < B * 10) {
        int bb = tid / 10, jj = tid % 10;
        float d = g_d[bb * NH + c_contact_idx[jj]];
        if (d > 0.005f && d < 0.01f) {
            att_sum = d * d;
            att_cnt = 1;
        }
    }

    // block reduction: warp shuffles then shared
    __shared__ float s_f[3][32];
    __shared__ int   s_i[2][32];
    const unsigned FULL = 0xffffffffu;
    for (int off = 16; off > 0; off >>= 1) {
        sum_d   += __shfl_down_sync(FULL, sum_d,   off);
        pen_sum += __shfl_down_sync(FULL, pen_sum, off);
        att_sum += __shfl_down_sync(FULL, att_sum, off);
        pen_cnt += __shfl_down_sync(FULL, pen_cnt, off);
        att_cnt += __shfl_down_sync(FULL, att_cnt, off);
    }
    int wid = tid >> 5, lid = tid & 31;
    if (lid == 0) {
        s_f[0][wid] = sum_d; s_f[1][wid] = pen_sum; s_f[2][wid] = att_sum;
        s_i[0][wid] = pen_cnt; s_i[1][wid] = att_cnt;
    }
    __syncthreads();
    if (tid == 0) {
        float tsum = 0.f, tpen = 0.f, tatt = 0.f;
        int   cpen = 0, catt = 0;
        #pragma unroll
        for (int w = 0; w < 32; w++) {
            tsum += s_f[0][w]; tpen += s_f[1][w]; tatt += s_f[2][w];
            cpen += s_i[0][w]; catt += s_i[1][w];
        }
        float pen_loss = (cpen > 0) ? tpen / (float)cpen : 0.f;
        float att_loss = (catt > 0) ? tatt / (float)catt : 0.f;
        float contact_loss = 100.f * pen_loss + 10.f * att_loss;
        float dist_mean = tsum / (float)N;
        out[0] = contact_loss;
        out[1] = pen_loss;
        out[2] = att_loss;
        out[3] = dist_mean;
        out[4] = (float)catt;  // num_contacts
        out[5] = (float)cpen;  // num_penetrations
    }
}

extern "C" void kernel_launch(void* const* d_in, const int* in_sizes, int n_in,
                              void* d_out, int out_size)
{
    const float* hand = (const float*)d_in[0];  // [8, 778, 3] f32
    const float* obj  = (const float*)d_in[1];  // [8, 40000, 3] f32
    // d_in[2], d_in[3] (faces) are unused by the loss
    float* out = (float*)d_out;

    dim3 grid(HTILES, OSLICES, B);
    mindist_kernel<<<grid, THREADS>>>(hand, obj);
    reduce_kernel<<<1, 1024>>>(out);
    (void)in_sizes; (void)n_in; (void)out_size;
}

// round 3
// speedup vs baseline: 2.0589x; 1.6857x over previous
#include <cuda_runtime.h>
#include <stdint.h>

#define B       8
#define NH      778
#define VOBJ    40000
#define NTOT    (B * NH)          // 6224
#define THREADS 224               // 7 warps
#define HREG    4                 // hand verts per thread: 224*4 = 896 >= 778
#define OSLICES 37                // 37*8 = 296 blocks = exactly 2 per SM
#define OSLICE  1082              // ceil(40000/37); last slice shorter (1048)
#define TOBJ    512               // shared tile of obj verts (256 packed pairs)
#define NPAIRS  (TOBJ / 2)

__constant__ int c_contact_idx[10] = {745, 317, 444, 556, 673, 95, 182, 234, 279, 320};

// per-slice partial d^2: [OSLICES][B][NH] — fully rewritten each launch
__device__ float g_part[OSLICES * NTOT];
// stage-A per-block partials: [25] x {sum_d, pen_sum, att_sum, pen_cnt, att_cnt}
__device__ float g_red_f[25 * 3];
__device__ int   g_red_i[25 * 2];

__device__ __forceinline__ unsigned long long pack2(float a, float b) {
    unsigned long long r;
    asm("mov.b64 %0, {%1, %2};" : "=l"(r) : "f"(a), "f"(b));
    return r;
}
__device__ __forceinline__ unsigned long long fma2(unsigned long long a,
                                                   unsigned long long b,
                                                   unsigned long long c) {
    unsigned long long d;
    asm("fma.rn.f32x2 %0, %1, %2, %3;" : "=l"(d) : "l"(a), "l"(b), "l"(c));
    return d;
}
__device__ __forceinline__ void unpack2(unsigned long long v, float& lo, float& hi) {
    asm("mov.b64 {%0, %1}, %2;" : "=f"(lo), "=f"(hi) : "l"(v));
}

__global__ __launch_bounds__(THREADS) void mindist_kernel(
    const float* __restrict__ hand, const float* __restrict__ obj)
{
    const int b     = blockIdx.z;
    const int slice = blockIdx.y;
    const int t     = threadIdx.x;

    // each thread owns HREG hand verts: h = t + k*THREADS (strided -> coalesced loads)
    unsigned long long axx[HREG], ayy[HREG], azz[HREG];
    float asq[HREG];
    #pragma unroll
    for (int k = 0; k < HREG; k++) {
        int h  = t + k * THREADS;
        int hc = (h < NH) ? h : 0;          // clamp: garbage lanes compute on vert 0
        const float* hp = hand + ((size_t)b * NH + hc) * 3;
        float ax = hp[0], ay = hp[1], az = hp[2];
        asq[k] = fmaf(ax, ax, fmaf(ay, ay, az * az));
        axx[k] = pack2(ax, ax);
        ayy[k] = pack2(ay, ay);
        azz[k] = pack2(az, az);
    }

    // packed-pair SoA: shA[p]={(-2x0,-2x1),(-2y0,-2y1)}, shB[p]={(-2z0,-2z1),(bsq0,bsq1)}
    __shared__ ulonglong2 shA[NPAIRS];
    __shared__ ulonglong2 shB[NPAIRS];

    const int o0 = slice * OSLICE;
    const int o1 = min(o0 + OSLICE, VOBJ);

    float m0[HREG], m1[HREG];
    #pragma unroll
    for (int k = 0; k < HREG; k++) { m0[k] = 3.4e38f; m1[k] = 3.4e38f; }

    for (int base = o0; base < o1; base += TOBJ) {
        const int cnt   = min(TOBJ, o1 - base);   // always even (1082/1048 slices)
        const int npair = cnt >> 1;
        __syncthreads();
        for (int k = t; k < npair; k += THREADS) {
            const float* op = obj + ((size_t)b * VOBJ + base + k * 2) * 3;
            float2 p01 = *(const float2*)(op + 0);   // x0 y0
            float2 p23 = *(const float2*)(op + 2);   // z0 x1
            float2 p45 = *(const float2*)(op + 4);   // y1 z1
            float x0 = p01.x, y0 = p01.y, z0 = p23.x;
            float x1 = p23.y, y1 = p45.x, z1 = p45.y;
            float w0 = fmaf(x0, x0, fmaf(y0, y0, z0 * z0));
            float w1 = fmaf(x1, x1, fmaf(y1, y1, z1 * z1));
            ulonglong2 A, Bv;
            A.x  = pack2(-2.f * x0, -2.f * x1);
            A.y  = pack2(-2.f * y0, -2.f * y1);
            Bv.x = pack2(-2.f * z0, -2.f * z1);
            Bv.y = pack2(w0, w1);
            shA[k] = A;
            shB[k] = Bv;
        }
        __syncthreads();

        #pragma unroll 2
        for (int p = 0; p < npair; ++p) {
            ulonglong2 A  = shA[p];
            ulonglong2 Bv = shB[p];
            #pragma unroll
            for (int k = 0; k < HREG; k++) {
                unsigned long long e =
                    fma2(A.x, axx[k], fma2(A.y, ayy[k], fma2(Bv.x, azz[k], Bv.y)));
                float e0, e1;
                unpack2(e, e0, e1);
                m0[k] = fminf(m0[k], e0);
                m1[k] = fminf(m1[k], e1);
            }
        }
    }

    float* dst = g_part + (size_t)(slice * B + b) * NH;
    #pragma unroll
    for (int k = 0; k < HREG; k++) {
        int h = t + k * THREADS;
        if (h < NH) dst[h] = asq[k] + fminf(m0[k], m1[k]);   // d^2 (clamped later)
    }
}

// stage A: 25 blocks x 256 threads — slice-min per vertex + per-block partial sums
__global__ __launch_bounds__(256) void reduceA_kernel()
{
    const int tid = threadIdx.x;
    const int i   = blockIdx.x * 256 + tid;

    float sum_d = 0.f, pen_sum = 0.f, att_sum = 0.f;
    int   pen_cnt = 0, att_cnt = 0;

    if (i < NTOT) {
        float mn = 3.4e38f;
        #pragma unroll
        for (int s = 0; s < OSLICES; s++)
            mn = fminf(mn, g_part[(size_t)s * NTOT + i]);
        float d = sqrtf(fmaxf(mn, 0.f));
        sum_d = d;
        if (d < 0.005f) {
            float tt = 0.005f - d;
            pen_sum = tt * tt;
            pen_cnt = 1;
        }
        int h = i % NH;
        bool is_contact = false;
        #pragma unroll
        for (int j = 0; j < 10; j++) is_contact |= (h == c_contact_idx[j]);
        if (is_contact && d > 0.005f && d < 0.01f) {
            att_sum = d * d;
            att_cnt = 1;
        }
    }

    __shared__ float s_f[3][8];
    __shared__ int   s_i[2][8];
    const unsigned FULL = 0xffffffffu;
    for (int off = 16; off > 0; off >>= 1) {
        sum_d   += __shfl_down_sync(FULL, sum_d,   off);
        pen_sum += __shfl_down_sync(FULL, pen_sum, off);
        att_sum += __shfl_down_sync(FULL, att_sum, off);
        pen_cnt += __shfl_down_sync(FULL, pen_cnt, off);
        att_cnt += __shfl_down_sync(FULL, att_cnt, off);
    }
    int wid = tid >> 5, lid = tid & 31;
    if (lid == 0) {
        s_f[0][wid] = sum_d; s_f[1][wid] = pen_sum; s_f[2][wid] = att_sum;
        s_i[0][wid] = pen_cnt; s_i[1][wid] = att_cnt;
    }
    __syncthreads();
    if (tid == 0) {
        float a = 0.f, c = 0.f, e = 0.f;
        int   p = 0, q = 0;
        #pragma unroll
        for (int w = 0; w < 8; w++) {
            a += s_f[0][w]; c += s_f[1][w]; e += s_f[2][w];
            p += s_i[0][w]; q += s_i[1][w];
        }
        g_red_f[blockIdx.x * 3 + 0] = a;
        g_red_f[blockIdx.x * 3 + 1] = c;
        g_red_f[blockIdx.x * 3 + 2] = e;
        g_red_i[blockIdx.x * 2 + 0] = p;
        g_red_i[blockIdx.x * 2 + 1] = q;
    }
}

// stage B: one warp combines the 25 block partials
__global__ void reduceB_kernel(float* __restrict__ out)
{
    const int lid = threadIdx.x;
    float sum_d = 0.f, pen_sum = 0.f, att_sum = 0.f;
    int   pen_cnt = 0, att_cnt = 0;
    if (lid < 25) {
        sum_d   = g_red_f[lid * 3 + 0];
        pen_sum = g_red_f[lid * 3 + 1];
        att_sum = g_red_f[lid * 3 + 2];
        pen_cnt = g_red_i[lid * 2 + 0];
        att_cnt = g_red_i[lid * 2 + 1];
    }
    const unsigned FULL = 0xffffffffu;
    for (int off = 16; off > 0; off >>= 1) {
        sum_d   += __shfl_down_sync(FULL, sum_d,   off);
        pen_sum += __shfl_down_sync(FULL, pen_sum, off);
        att_sum += __shfl_down_sync(FULL, att_sum, off);
        pen_cnt += __shfl_down_sync(FULL, pen_cnt, off);
        att_cnt += __shfl_down_sync(FULL, att_cnt, off);
    }
    if (lid == 0) {
        float pen_loss = (pen_cnt > 0) ? pen_sum / (float)pen_cnt : 0.f;
        float att_loss = (att_cnt > 0) ? att_sum / (float)att_cnt : 0.f;
        out[0] = 100.f * pen_loss + 10.f * att_loss;
        out[1] = pen_loss;
        out[2] = att_loss;
        out[3] = sum_d / (float)NTOT;
        out[4] = (float)att_cnt;   // num_contacts
        out[5] = (float)pen_cnt;   // num_penetrations
    }
}

extern "C" void kernel_launch(void* const* d_in, const int* in_sizes, int n_in,
                              void* d_out, int out_size)
{
    const float* hand = (const float*)d_in[0];  // [8, 778, 3] f32
    const float* obj  = (const float*)d_in[1];  // [8, 40000, 3] f32
    float* out = (float*)d_out;

    dim3 grid(1, OSLICES, B);                   // 296 blocks = 2/SM
    mindist_kernel<<<grid, THREADS>>>(hand, obj);
    reduceA_kernel<<<25, 256>>>();
    reduceB_kernel<<<1, 32>>>(out);
    (void)in_sizes; (void)n_in; (void)out_size;
}

// round 4
// speedup vs baseline: 2.1299x; 1.0345x over previous
#include <cuda_runtime.h>
#include <stdint.h>

#define B       8
#define NH      778
#define VOBJ    40000
#define NTOT    (B * NH)          // 6224
#define THREADS 160               // 5 warps
#define HREG    5                 // 160*5 = 800 >= 778 (2.8% waste)
#define OSLICES 74                // 74*8 = 592 blocks = exactly 4 per SM
#define OSLICE  542               // even; 542*73 + 434 = 40000
#define NPAIRS  (OSLICE / 2)      // 271 packed pairs max per block

__constant__ int c_contact_idx[10] = {745, 317, 444, 556, 673, 95, 182, 234, 279, 320};

// per-slice partial d^2: [OSLICES][B][NH] — fully rewritten each launch
__device__ float g_part[OSLICES * NTOT];
// stage-A per-block partials
__device__ float g_red_f[25 * 3];
__device__ int   g_red_i[25 * 2];

__device__ __forceinline__ unsigned long long pack2(float a, float b) {
    unsigned long long r;
    asm("mov.b64 %0, {%1, %2};" : "=l"(r) : "f"(a), "f"(b));
    return r;
}
__device__ __forceinline__ unsigned long long fma2(unsigned long long a,
                                                   unsigned long long b,
                                                   unsigned long long c) {
    unsigned long long d;
    asm("fma.rn.f32x2 %0, %1, %2, %3;" : "=l"(d) : "l"(a), "l"(b), "l"(c));
    return d;
}
__device__ __forceinline__ void unpack2(unsigned long long v, float& lo, float& hi) {
    asm("mov.b64 {%0, %1}, %2;" : "=f"(lo), "=f"(hi) : "l"(v));
}

__global__ __launch_bounds__(THREADS) void mindist_kernel(
    const float* __restrict__ hand, const float* __restrict__ obj)
{
    const int b     = blockIdx.z;
    const int slice = blockIdx.y;
    const int t     = threadIdx.x;

    // each thread owns HREG hand verts: h = t + k*THREADS (coalesced loads)
    unsigned long long axx[HREG], ayy[HREG], azz[HREG];
    float asq[HREG];
    #pragma unroll
    for (int k = 0; k < HREG; k++) {
        int h  = t + k * THREADS;
        int hc = (h < NH) ? h : 0;          // clamp: spare lanes recompute vert 0
        const float* hp = hand + ((size_t)b * NH + hc) * 3;
        float ax = hp[0], ay = hp[1], az = hp[2];
        asq[k] = fmaf(ax, ax, fmaf(ay, ay, az * az));
        axx[k] = pack2(ax, ax);
        ayy[k] = pack2(ay, ay);
        azz[k] = pack2(az, az);
    }

    // packed-pair SoA: shA[p]={(-2x0,-2x1),(-2y0,-2y1)}, shB[p]={(-2z0,-2z1),(bsq0,bsq1)}
    __shared__ ulonglong2 shA[NPAIRS];
    __shared__ ulonglong2 shB[NPAIRS];

    const int o0    = slice * OSLICE;
    const int cnt   = min(OSLICE, VOBJ - o0);    // 542 or 434 (both even)
    const int npair = cnt >> 1;

    // single tile fill (271 pairs / 160 threads = 2 rounds)
    for (int k = t; k < npair; k += THREADS) {
        const float* op = obj + ((size_t)b * VOBJ + o0 + k * 2) * 3;
        float2 p01 = *(const float2*)(op + 0);   // x0 y0
        float2 p23 = *(const float2*)(op + 2);   // z0 x1
        float2 p45 = *(const float2*)(op + 4);   // y1 z1
        float x0 = p01.x, y0 = p01.y, z0 = p23.x;
        float x1 = p23.y, y1 = p45.x, z1 = p45.y;
        float w0 = fmaf(x0, x0, fmaf(y0, y0, z0 * z0));
        float w1 = fmaf(x1, x1, fmaf(y1, y1, z1 * z1));
        ulonglong2 A, Bv;
        A.x  = pack2(-2.f * x0, -2.f * x1);
        A.y  = pack2(-2.f * y0, -2.f * y1);
        Bv.x = pack2(-2.f * z0, -2.f * z1);
        Bv.y = pack2(w0, w1);
        shA[k] = A;
        shB[k] = Bv;
    }
    __syncthreads();

    float m0[HREG], m1[HREG];
    #pragma unroll
    for (int k = 0; k < HREG; k++) { m0[k] = 3.4e38f; m1[k] = 3.4e38f; }

    #pragma unroll 2
    for (int p = 0; p < npair; ++p) {
        ulonglong2 A  = shA[p];
        ulonglong2 Bv = shB[p];
        #pragma unroll
        for (int k = 0; k < HREG; k++) {
            unsigned long long e =
                fma2(A.x, axx[k], fma2(A.y, ayy[k], fma2(Bv.x, azz[k], Bv.y)));
            float e0, e1;
            unpack2(e, e0, e1);
            m0[k] = fminf(m0[k], e0);
            m1[k] = fminf(m1[k], e1);
        }
    }

    float* dst = g_part + (size_t)(slice * B + b) * NH;
    #pragma unroll
    for (int k = 0; k < HREG; k++) {
        int h = t + k * THREADS;
        if (h < NH) dst[h] = asq[k] + fminf(m0[k], m1[k]);   // d^2 (clamped later)
    }
}

// stage A: 25 blocks x 256 threads — slice-min per vertex + per-block partial sums
__global__ __launch_bounds__(256) void reduceA_kernel()
{
    const int tid = threadIdx.x;
    const int i   = blockIdx.x * 256 + tid;

    float sum_d = 0.f, pen_sum = 0.f, att_sum = 0.f;
    int   pen_cnt = 0, att_cnt = 0;

    if (i < NTOT) {
        float mn = 3.4e38f;
        #pragma unroll 4
        for (int s = 0; s < OSLICES; s++)
            mn = fminf(mn, g_part[(size_t)s * NTOT + i]);
        float d = sqrtf(fmaxf(mn, 0.f));
        sum_d = d;
        if (d < 0.005f) {
            float tt = 0.005f - d;
            pen_sum = tt * tt;
            pen_cnt = 1;
        }
        int h = i % NH;
        bool is_contact = false;
        #pragma unroll
        for (int j = 0; j < 10; j++) is_contact |= (h == c_contact_idx[j]);
        if (is_contact && d > 0.005f && d < 0.01f) {
            att_sum = d * d;
            att_cnt = 1;
        }
    }

    __shared__ float s_f[3][8];
    __shared__ int   s_i[2][8];
    const unsigned FULL = 0xffffffffu;
    for (int off = 16; off > 0; off >>= 1) {
        sum_d   += __shfl_down_sync(FULL, sum_d,   off);
        pen_sum += __shfl_down_sync(FULL, pen_sum, off);
        att_sum += __shfl_down_sync(FULL, att_sum, off);
        pen_cnt += __shfl_down_sync(FULL, pen_cnt, off);
        att_cnt += __shfl_down_sync(FULL, att_cnt, off);
    }
    int wid = tid >> 5, lid = tid & 31;
    if (lid == 0) {
        s_f[0][wid] = sum_d; s_f[1][wid] = pen_sum; s_f[2][wid] = att_sum;
        s_i[0][wid] = pen_cnt; s_i[1][wid] = att_cnt;
    }
    __syncthreads();
    if (tid == 0) {
        float a = 0.f, c = 0.f, e = 0.f;
        int   p = 0, q = 0;
        #pragma unroll
        for (int w = 0; w < 8; w++) {
            a += s_f[0][w]; c += s_f[1][w]; e += s_f[2][w];
            p += s_i[0][w]; q += s_i[1][w];
        }
        g_red_f[blockIdx.x * 3 + 0] = a;
        g_red_f[blockIdx.x * 3 + 1] = c;
        g_red_f[blockIdx.x * 3 + 2] = e;
        g_red_i[blockIdx.x * 2 + 0] = p;
        g_red_i[blockIdx.x * 2 + 1] = q;
    }
}

// stage B: one warp combines the 25 block partials
__global__ void reduceB_kernel(float* __restrict__ out)
{
    const int lid = threadIdx.x;
    float sum_d = 0.f, pen_sum = 0.f, att_sum = 0.f;
    int   pen_cnt = 0, att_cnt = 0;
    if (lid < 25) {
        sum_d   = g_red_f[lid * 3 + 0];
        pen_sum = g_red_f[lid * 3 + 1];
        att_sum = g_red_f[lid * 3 + 2];
        pen_cnt = g_red_i[lid * 2 + 0];
        att_cnt = g_red_i[lid * 2 + 1];
    }
    const unsigned FULL = 0xffffffffu;
    for (int off = 16; off > 0; off >>= 1) {
        sum_d   += __shfl_down_sync(FULL, sum_d,   off);
        pen_sum += __shfl_down_sync(FULL, pen_sum, off);
        att_sum += __shfl_down_sync(FULL, att_sum, off);
        pen_cnt += __shfl_down_sync(FULL, pen_cnt, off);
        att_cnt += __shfl_down_sync(FULL, att_cnt, off);
    }
    if (lid == 0) {
        float pen_loss = (pen_cnt > 0) ? pen_sum / (float)pen_cnt : 0.f;
        float att_loss = (att_cnt > 0) ? att_sum / (float)att_cnt : 0.f;
        out[0] = 100.f * pen_loss + 10.f * att_loss;
        out[1] = pen_loss;
        out[2] = att_loss;
        out[3] = sum_d / (float)NTOT;
        out[4] = (float)att_cnt;   // num_contacts
        out[5] = (float)pen_cnt;   // num_penetrations
    }
}

extern "C" void kernel_launch(void* const* d_in, const int* in_sizes, int n_in,
                              void* d_out, int out_size)
{
    const float* hand = (const float*)d_in[0];  // [8, 778, 3] f32
    const float* obj  = (const float*)d_in[1];  // [8, 40000, 3] f32
    float* out = (float*)d_out;

    dim3 grid(1, OSLICES, B);                   // 592 blocks = 4/SM
    mindist_kernel<<<grid, THREADS>>>(hand, obj);
    reduceA_kernel<<<25, 256>>>();
    reduceB_kernel<<<1, 32>>>(out);
    (void)in_sizes; (void)n_in; (void)out_size;
}

// round 5
// speedup vs baseline: 2.2892x; 1.0748x over previous
#include <cuda_runtime.h>
#include <stdint.h>

#define B       8
#define NH      778
#define VOBJ    40000
#define NTOT    (B * NH)          // 6224
#define THREADS 160               // 5 warps
#define HREG    5                 // 160*5 = 800 >= 778 (2.8% waste)
#define OSLICES 148               // 148*8 = 1184 blocks = exactly 8 per SM
#define OSLICE  272               // even; 272*147 + 16 = 40000
#define NPAIRS  (OSLICE / 2)      // 136 packed pairs max per block

__constant__ int c_contact_idx[10] = {745, 317, 444, 556, 673, 95, 182, 234, 279, 320};

// per-slice partial d^2: [OSLICES][B][NH] — fully rewritten each launch
__device__ float g_part[OSLICES * NTOT];
// stage-A per-block partials
__device__ float g_red_f[25 * 3];
__device__ int   g_red_i[25 * 2];

__device__ __forceinline__ unsigned long long pack2(float a, float b) {
    unsigned long long r;
    asm("mov.b64 %0, {%1, %2};" : "=l"(r) : "f"(a), "f"(b));
    return r;
}
__device__ __forceinline__ unsigned long long fma2(unsigned long long a,
                                                   unsigned long long b,
                                                   unsigned long long c) {
    unsigned long long d;
    asm("fma.rn.f32x2 %0, %1, %2, %3;" : "=l"(d) : "l"(a), "l"(b), "l"(c));
    return d;
}
__device__ __forceinline__ void unpack2(unsigned long long v, float& lo, float& hi) {
    asm("mov.b64 {%0, %1}, %2;" : "=f"(lo), "=f"(hi) : "l"(v));
}

__global__ __launch_bounds__(THREADS, 8) void mindist_kernel(
    const float* __restrict__ hand, const float* __restrict__ obj)
{
    const int b     = blockIdx.z;
    const int slice = blockIdx.y;
    const int t     = threadIdx.x;

    // each thread owns HREG hand verts: h = t + k*THREADS (coalesced loads)
    unsigned long long axx[HREG], ayy[HREG], azz[HREG];
    float asq[HREG];
    #pragma unroll
    for (int k = 0; k < HREG; k++) {
        int h  = t + k * THREADS;
        int hc = (h < NH) ? h : 0;          // clamp: spare lanes recompute vert 0
        const float* hp = hand + ((size_t)b * NH + hc) * 3;
        float ax = hp[0], ay = hp[1], az = hp[2];
        asq[k] = fmaf(ax, ax, fmaf(ay, ay, az * az));
        axx[k] = pack2(ax, ax);
        ayy[k] = pack2(ay, ay);
        azz[k] = pack2(az, az);
    }

    // packed-pair SoA: shA[p]={(-2x0,-2x1),(-2y0,-2y1)}, shB[p]={(-2z0,-2z1),(bsq0,bsq1)}
    __shared__ ulonglong2 shA[NPAIRS];
    __shared__ ulonglong2 shB[NPAIRS];

    const int o0    = slice * OSLICE;
    const int cnt   = min(OSLICE, VOBJ - o0);    // 272 or 16 (both even)
    const int npair = cnt >> 1;                  // 136 or 8 (both %4 == 0)

    // single tile fill (136 pairs / 160 threads = 1 round)
    for (int k = t; k < npair; k += THREADS) {
        const float* op = obj + ((size_t)b * VOBJ + o0 + k * 2) * 3;
        float2 p01 = *(const float2*)(op + 0);   // x0 y0
        float2 p23 = *(const float2*)(op + 2);   // z0 x1
        float2 p45 = *(const float2*)(op + 4);   // y1 z1
        float x0 = p01.x, y0 = p01.y, z0 = p23.x;
        float x1 = p23.y, y1 = p45.x, z1 = p45.y;
        float w0 = fmaf(x0, x0, fmaf(y0, y0, z0 * z0));
        float w1 = fmaf(x1, x1, fmaf(y1, y1, z1 * z1));
        ulonglong2 A, Bv;
        A.x  = pack2(-2.f * x0, -2.f * x1);
        A.y  = pack2(-2.f * y0, -2.f * y1);
        Bv.x = pack2(-2.f * z0, -2.f * z1);
        Bv.y = pack2(w0, w1);
        shA[k] = A;
        shB[k] = Bv;
    }
    __syncthreads();

    float m0[HREG], m1[HREG];
    #pragma unroll
    for (int k = 0; k < HREG; k++) { m0[k] = 3.4e38f; m1[k] = 3.4e38f; }

    #pragma unroll 4
    for (int p = 0; p < npair; ++p) {
        ulonglong2 A  = shA[p];
        ulonglong2 Bv = shB[p];
        #pragma unroll
        for (int k = 0; k < HREG; k++) {
            unsigned long long e =
                fma2(A.x, axx[k], fma2(A.y, ayy[k], fma2(Bv.x, azz[k], Bv.y)));
            float e0, e1;
            unpack2(e, e0, e1);
            m0[k] = fminf(m0[k], e0);
            m1[k] = fminf(m1[k], e1);
        }
    }

    float* dst = g_part + (size_t)(slice * B + b) * NH;
    #pragma unroll
    for (int k = 0; k < HREG; k++) {
        int h = t + k * THREADS;
        if (h < NH) dst[h] = asq[k] + fminf(m0[k], m1[k]);   // d^2 (clamped later)
    }
}

// stage A: 25 blocks x 256 threads — slice-min per vertex + per-block partial sums
__global__ __launch_bounds__(256) void reduceA_kernel()
{
    const int tid = threadIdx.x;
    const int i   = blockIdx.x * 256 + tid;

    float sum_d = 0.f, pen_sum = 0.f, att_sum = 0.f;
    int   pen_cnt = 0, att_cnt = 0;

    if (i < NTOT) {
        // 4 independent accumulators -> MLP 4 against L2 latency
        float mn0 = 3.4e38f, mn1 = 3.4e38f, mn2 = 3.4e38f, mn3 = 3.4e38f;
        #pragma unroll 4
        for (int s = 0; s < OSLICES; s += 4) {
            mn0 = fminf(mn0, g_part[(size_t)(s + 0) * NTOT + i]);
            mn1 = fminf(mn1, g_part[(size_t)(s + 1) * NTOT + i]);
            mn2 = fminf(mn2, g_part[(size_t)(s + 2) * NTOT + i]);
            mn3 = fminf(mn3, g_part[(size_t)(s + 3) * NTOT + i]);
        }
        float mn = fminf(fminf(mn0, mn1), fminf(mn2, mn3));
        float d = sqrtf(fmaxf(mn, 0.f));
        sum_d = d;
        if (d < 0.005f) {
            float tt = 0.005f - d;
            pen_sum = tt * tt;
            pen_cnt = 1;
        }
        int h = i % NH;
        bool is_contact = false;
        #pragma unroll
        for (int j = 0; j < 10; j++) is_contact |= (h == c_contact_idx[j]);
        if (is_contact && d > 0.005f && d < 0.01f) {
            att_sum = d * d;
            att_cnt = 1;
        }
    }

    __shared__ float s_f[3][8];
    __shared__ int   s_i[2][8];
    const unsigned FULL = 0xffffffffu;
    for (int off = 16; off > 0; off >>= 1) {
        sum_d   += __shfl_down_sync(FULL, sum_d,   off);
        pen_sum += __shfl_down_sync(FULL, pen_sum, off);
        att_sum += __shfl_down_sync(FULL, att_sum, off);
        pen_cnt += __shfl_down_sync(FULL, pen_cnt, off);
        att_cnt += __shfl_down_sync(FULL, att_cnt, off);
    }
    int wid = tid >> 5, lid = tid & 31;
    if (lid == 0) {
        s_f[0][wid] = sum_d; s_f[1][wid] = pen_sum; s_f[2][wid] = att_sum;
        s_i[0][wid] = pen_cnt; s_i[1][wid] = att_cnt;
    }
    __syncthreads();
    if (tid == 0) {
        float a = 0.f, c = 0.f, e = 0.f;
        int   p = 0, q = 0;
        #pragma unroll
        for (int w = 0; w < 8; w++) {
            a += s_f[0][w]; c += s_f[1][w]; e += s_f[2][w];
            p += s_i[0][w]; q += s_i[1][w];
        }
        g_red_f[blockIdx.x * 3 + 0] = a;
        g_red_f[blockIdx.x * 3 + 1] = c;
        g_red_f[blockIdx.x * 3 + 2] = e;
        g_red_i[blockIdx.x * 2 + 0] = p;
        g_red_i[blockIdx.x * 2 + 1] = q;
    }
}

// stage B: one warp combines the 25 block partials
__global__ void reduceB_kernel(float* __restrict__ out)
{
    const int lid = threadIdx.x;
    float sum_d = 0.f, pen_sum = 0.f, att_sum = 0.f;
    int   pen_cnt = 0, att_cnt = 0;
    if (lid < 25) {
        sum_d   = g_red_f[lid * 3 + 0];
        pen_sum = g_red_f[lid * 3 + 1];
        att_sum = g_red_f[lid * 3 + 2];
        pen_cnt = g_red_i[lid * 2 + 0];
        att_cnt = g_red_i[lid * 2 + 1];
    }
    const unsigned FULL = 0xffffffffu;
    for (int off = 16; off > 0; off >>= 1) {
        sum_d   += __shfl_down_sync(FULL, sum_d,   off);
        pen_sum += __shfl_down_sync(FULL, pen_sum, off);
        att_sum += __shfl_down_sync(FULL, att_sum, off);
        pen_cnt += __shfl_down_sync(FULL, pen_cnt, off);
        att_cnt += __shfl_down_sync(FULL, att_cnt, off);
    }
    if (lid == 0) {
        float pen_loss = (pen_cnt > 0) ? pen_sum / (float)pen_cnt : 0.f;
        float att_loss = (att_cnt > 0) ? att_sum / (float)att_cnt : 0.f;
        out[0] = 100.f * pen_loss + 10.f * att_loss;
        out[1] = pen_loss;
        out[2] = att_loss;
        out[3] = sum_d / (float)NTOT;
        out[4] = (float)att_cnt;   // num_contacts
        out[5] = (float)pen_cnt;   // num_penetrations
    }
}

extern "C" void kernel_launch(void* const* d_in, const int* in_sizes, int n_in,
                              void* d_out, int out_size)
{
    const float* hand = (const float*)d_in[0];  // [8, 778, 3] f32
    const float* obj  = (const float*)d_in[1];  // [8, 40000, 3] f32
    float* out = (float*)d_out;

    dim3 grid(1, OSLICES, B);                   // 1184 blocks = 8/SM
    mindist_kernel<<<grid, THREADS>>>(hand, obj);
    reduceA_kernel<<<25, 256>>>();
    reduceB_kernel<<<1, 32>>>(out);
    (void)in_sizes; (void)n_in; (void)out_size;
}